// round 8
// baseline (speedup 1.0000x reference)
#include <cuda_runtime.h>
#include <cuda_bf16.h>
#include <math.h>
#include <stdint.h>

// ---------------------------------------------------------------------------
// Problem constants
// ---------------------------------------------------------------------------
#define BATCH   4
#define HW      4096
#define BN_EPS  1e-5f
#define VPIX    5440
#define VSTRF   (VPIX*256)
#define ABF     512                  // bf16 activation row: [256 hi][256 lo]

__device__ __constant__ int c_voff[4]  = {0, 1048576, 1310720, 1376256};
__device__ __constant__ int c_vpix[4]  = {0, 4096, 5120, 5376};
__device__ __constant__ int c_mact[4]  = {4096, 1024, 256, 64};
__device__ __constant__ int c_vts[5]   = {0, 32, 40, 42, 43};
__device__ __constant__ int c_fts[6]   = {0, 128, 256, 288, 296, 298};
__device__ __constant__ int c_tapd[9]  = {-33280, -32768, -32256, -512, 0, 512,
                                           32256, 32768, 33280};

// ---------------------------------------------------------------------------
// Scratch
// ---------------------------------------------------------------------------
__device__ __nv_bfloat16 g_qT [BATCH * HW * ABF];
__device__ __nv_bfloat16 g_fT [BATCH * VPIX * ABF];
__device__ __nv_bfloat16 g_att[BATCH * HW * ABF];
__device__ __nv_bfloat16 g_Woa[3456 * ABF];
__device__ __nv_bfloat16 g_qwT[256 * ABF];
__device__ __nv_bfloat16 g_vw [4 * 256 * ABF];
__device__ __nv_bfloat16 g_ow [256 * ABF];
__device__ __nv_bfloat16 g_Wc [384 * 4608];
__device__ float g_v  [BATCH * VSTRF];
__device__ float g_cv [BATCH * HW * 384];
__device__ float g_cb [384];
__device__ float g_bns[256], g_bnb[256];

// ---------------------------------------------------------------------------
// Helpers
// ---------------------------------------------------------------------------
__device__ __forceinline__ uint32_t smem_u32(const void* p) {
    uint32_t a;
    asm("{ .reg .u64 t; cvta.to.shared.u64 t, %1; cvt.u32.u64 %0, t; }"
        : "=r"(a) : "l"(p));
    return a;
}
__device__ __forceinline__ void cp16(uint32_t dst, const void* src, bool v) {
    int sz = v ? 16 : 0;
    asm volatile("cp.async.cg.shared.global [%0], [%1], 16, %2;\n"
                 :: "r"(dst), "l"(src), "r"(sz) : "memory");
}
__device__ __forceinline__ void cp_commit() {
    asm volatile("cp.async.commit_group;\n" ::: "memory");
}
__device__ __forceinline__ void cp_wait1() {
    asm volatile("cp.async.wait_group 1;\n" ::: "memory");
}
__device__ __forceinline__ void mma_bf16(float* c, const uint32_t* a, const uint32_t* b) {
    asm volatile(
        "mma.sync.aligned.m16n8k16.row.col.f32.bf16.bf16.f32 "
        "{%0,%1,%2,%3}, {%4,%5,%6,%7}, {%8,%9}, {%0,%1,%2,%3};"
        : "+f"(c[0]), "+f"(c[1]), "+f"(c[2]), "+f"(c[3])
        : "r"(a[0]), "r"(a[1]), "r"(a[2]), "r"(a[3]), "r"(b[0]), "r"(b[1]));
}
#define LDSM_X4(r0, r1, r2, r3, addr) \
    asm volatile("ldmatrix.sync.aligned.m8n8.x4.shared.b16 {%0,%1,%2,%3}, [%4];" \
        : "=r"(r0), "=r"(r1), "=r"(r2), "=r"(r3) : "r"(addr))

__device__ __forceinline__ void split_bf(float x, __nv_bfloat16& h, __nv_bfloat16& l) {
    h = __float2bfloat16(x);
    l = __float2bfloat16(x - __bfloat162float(h));
}

// compact swizzled smem: 128 rows x 128B per matrix-stage; 16B-chunk c of row r
// lives at physical chunk c ^ (r & 7).
#define STG_B    16384
#define DSMEM_SZ (6 * STG_B)          // 96 KB -> 2 CTAs/SM

// ---------------------------------------------------------------------------
// Unified split-bf16 GEMM. 128 threads = 4 warps (2m x 2n), warp tile 64x64.
// lmode: 0=compose, 1=merged conv+vproj, 3=outproj.
// D[128m][128n] = sum_k A[m][k]*B[n][k], 3-term bf16 m16n8k16.
// 3-stage cp.async ring, ONE __syncthreads per stage, wait_group 1.
// ---------------------------------------------------------------------------
__global__ __launch_bounds__(128)
void mm_all(int lmode, const float* __restrict__ resid, float* __restrict__ outp)
{
    extern __shared__ float sm[];

    const int b    = blockIdx.z;
    const int tid  = threadIdx.x;
    const int wid  = tid >> 5;
    const int lane = tid & 31;
    const int wm   = wid >> 1;          // 0..1
    const int wn   = wid & 1;           // 0..1
    const int gid  = lane >> 2;
    const int tig  = lane & 3;
    const int l8   = lane & 7;
    const int lm   = (lane >> 3) & 1;
    const int lh   = lane >> 4;

    // ---- per-CTA mode & geometry ----
    int mode, m0, n0, NK, KB, lvl = 0, M_act = 1 << 30;
    const __nv_bfloat16 *Abase, *Bbase;
    if (lmode == 1) {
        int t = blockIdx.x;
        if (t < 96) {
            mode = 1; m0 = (t & 31) * 128; n0 = (t >> 5) * 128;
            NK = 72; KB = 2304;
            Abase = g_qT + (long)b * HW * ABF;
            Bbase = g_Wc;
        } else {
            mode = 2; int tv = t - 96;
            int nt = (tv >= 43) ? 1 : 0;
            int mtile = tv - nt * 43;
            while (mtile >= c_vts[lvl + 1]) lvl++;
            m0 = (mtile - c_vts[lvl]) * 128;
            n0 = nt * 128;
            M_act = c_mact[lvl];
            NK = 8; KB = 256;
            Abase = g_fT + (long)b * VPIX * ABF + (long)c_vpix[lvl] * ABF;
            Bbase = g_vw + lvl * 256 * ABF;
        }
    } else if (lmode == 0) {
        mode = 0; m0 = blockIdx.x * 128; n0 = blockIdx.y * 128;
        NK = 8; KB = 256;
        Abase = g_Woa; Bbase = g_qwT;
        M_act = 3456;
    } else {
        mode = 3; m0 = blockIdx.x * 128; n0 = blockIdx.y * 128;
        NK = 8; KB = 256;
        Abase = g_att + (long)b * HW * ABF; Bbase = g_ow;
    }
    const bool isConv = (mode == 1);

    // ---- hoisted loader state (128 threads: 16-row base, 8 row-groups) ----
    const int r0    = tid >> 3;         // 0..15
    const int sub   = tid & 7;
    const int plane = sub >> 2;
    const int kc    = sub & 3;
    const int phys  = sub ^ (r0 & 7);   // row&7 invariant under +16
    const uint32_t smb = smem_u32(sm);

    const __nv_bfloat16* aB = Abase + (long)(m0 + r0) * ABF + plane * 256 + kc * 8;
    const __nv_bfloat16* bP = Bbase + (long)(n0 + r0) * (2 * KB) + plane * KB + kc * 8;
    const int aRowStep = 16 * ABF;
    const int bRowStep = 16 * (2 * KB);
    const uint32_t dA0 = smb + r0 * 128 + phys * 16;
    const uint32_t dB0 = dA0 + 3 * STG_B;

    // validity masks: 9 bits per row-group
    uint32_t vmask[8];
#pragma unroll
    for (int i = 0; i < 8; i++) {
        if (isConv) {
            int pix = m0 + r0 + 16 * i;
            int py0 = pix >> 6, px0 = pix & 63;
            uint32_t m9 = 0;
#pragma unroll
            for (int tp = 0; tp < 9; tp++) {
                int py = py0 + tp / 3 - 1, px = px0 + tp % 3 - 1;
                if (py >= 0 && py < 64 && px >= 0 && px < 64) m9 |= 1u << tp;
            }
            vmask[i] = m9;
        } else {
            vmask[i] = ((m0 + r0 + 16 * i) < M_act) ? 0x1FFu : 0u;
        }
    }

    float acc[4][8][4];
#pragma unroll
    for (int mt = 0; mt < 4; mt++)
#pragma unroll
        for (int nt = 0; nt < 8; nt++)
#pragma unroll
            for (int r = 0; r < 4; r++) acc[mt][nt][r] = 0.f;

    auto load_stage = [&](int s, int buf) {
        const int tap  = s >> 3;
        const int aoff = (isConv ? c_tapd[tap] : 0) + ((s & 7) << 5);
        const __nv_bfloat16* ap = aB + aoff;
        const __nv_bfloat16* bp = bP + s * 32;
        const uint32_t dA = dA0 + buf * STG_B;
        const uint32_t dB = dB0 + buf * STG_B;
#pragma unroll
        for (int i = 0; i < 8; i++) {
            bool v = (vmask[i] >> tap) & 1;
            cp16(dA + i * 2048, v ? (ap + i * aRowStep) : (const void*)Abase, v);
            cp16(dB + i * 2048, bp + i * bRowStep, true);
        }
    };

    // prologue: 2 stages in flight
    load_stage(0, 0); cp_commit();
    if (NK > 1) load_stage(1, 1); cp_commit();

    for (int s = 0; s < NK; s++) {
        const int buf = s % 3;
        cp_wait1();                 // group s complete
        __syncthreads();            // also: all warps done with buffer (s+2)%3
        if (s + 2 < NK) load_stage(s + 2, (s + 2) % 3);
        cp_commit();

        const uint32_t aBase_s = smb + buf * STG_B;
        const uint32_t bBase_s = smb + (3 + buf) * STG_B;
#pragma unroll
        for (int kk = 0; kk < 2; kk++) {
            const int chH = kk * 2 + lh;
            const int chL = chH + 4;
            uint32_t ah[4][4], al[4][4];
#pragma unroll
            for (int mt = 0; mt < 4; mt++) {
                int row = wm * 64 + mt * 16 + l8 + lm * 8;
                uint32_t base = aBase_s + row * 128;
                LDSM_X4(ah[mt][0], ah[mt][1], ah[mt][2], ah[mt][3],
                        base + ((chH ^ l8) << 4));
                LDSM_X4(al[mt][0], al[mt][1], al[mt][2], al[mt][3],
                        base + ((chL ^ l8) << 4));
            }
            // process B in two np-halves to limit live fragment registers
#pragma unroll
            for (int half = 0; half < 2; half++) {
                uint32_t bh[4][2], bl[4][2];
#pragma unroll
                for (int q = 0; q < 2; q++) {
                    int np = half * 2 + q;
                    int row = wn * 64 + np * 16 + l8 + lm * 8;
                    uint32_t base = bBase_s + row * 128;
                    LDSM_X4(bh[2 * q][0], bh[2 * q + 1][0],
                            bh[2 * q][1], bh[2 * q + 1][1],
                            base + ((chH ^ l8) << 4));
                    LDSM_X4(bl[2 * q][0], bl[2 * q + 1][0],
                            bl[2 * q][1], bl[2 * q + 1][1],
                            base + ((chL ^ l8) << 4));
                }
#pragma unroll
                for (int mt = 0; mt < 4; mt++)
#pragma unroll
                    for (int j = 0; j < 4; j++) {
                        int nt = half * 4 + j;
                        mma_bf16(acc[mt][nt], ah[mt], bh[j]);
                        mma_bf16(acc[mt][nt], ah[mt], bl[j]);
                        mma_bf16(acc[mt][nt], al[mt], bh[j]);
                    }
            }
        }
    }

    // ---- epilogues ----
#pragma unroll
    for (int mt = 0; mt < 4; mt++) {
        int r0e = m0 + wm * 64 + mt * 16 + gid;
#pragma unroll
        for (int nt = 0; nt < 8; nt++) {
            int col = n0 + wn * 64 + nt * 8 + tig * 2;
#pragma unroll
            for (int h = 0; h < 2; h++) {
                int r = r0e + h * 8;
                float vx = acc[mt][nt][2 * h];
                float vy = acc[mt][nt][2 * h + 1];
                if (mode == 0) {
                    int tap = r / 384, o = r - tap * 384;
                    long e = (long)o * 4608 + tap * 256 + col;
                    __nv_bfloat16 hh, ll;
                    split_bf(vx, hh, ll); g_Wc[e]     = hh; g_Wc[e + 2304]     = ll;
                    split_bf(vy, hh, ll); g_Wc[e + 1] = hh; g_Wc[e + 1 + 2304] = ll;
                } else if (mode == 1) {
                    float2 o = make_float2(vx + g_cb[col], vy + g_cb[col + 1]);
                    *(float2*)&g_cv[((long)b * HW + r) * 384 + col] = o;
                } else if (mode == 2) {
                    if (r < M_act) {
                        long row = c_vpix[lvl] + r;
                        *(float2*)&g_v[(long)b * VSTRF + row * 256 + col] =
                            make_float2(vx, vy);
                    }
                } else {
                    const float* qb = resid + (long)b * 256 * HW;
                    float* yb = outp + (long)b * 256 * HW;
#pragma unroll
                    for (int j = 0; j < 2; j++) {
                        int oc = col + j;
                        float x  = ((j == 0) ? vx : vy) + qb[(long)oc * HW + r];
                        float xn = x * g_bns[oc] + g_bnb[oc];
                        yb[(long)oc * HW + r] = xn / (1.f + expf(-xn));
                    }
                }
            }
        }
    }
}

// ---------------------------------------------------------------------------
// One transpose kernel for query + all 4 feature levels.
// ---------------------------------------------------------------------------
__global__ __launch_bounds__(256)
void transposeAll(const float* __restrict__ q,
                  const float* __restrict__ f0, const float* __restrict__ f1,
                  const float* __restrict__ f2, const float* __restrict__ f3,
                  __nv_bfloat16* __restrict__ oq, __nv_bfloat16* __restrict__ of)
{
    __shared__ float t[32][33];
    int sel = 0;
    while ((int)blockIdx.x >= c_fts[sel + 1]) sel++;
    const int tile0 = blockIdx.x - c_fts[sel];
    const int b = blockIdx.z;
    int P; const float* I; __nv_bfloat16* O;
    if (sel == 0) {
        P = 4096; I = q + (long)b * 256 * HW; O = oq + (long)b * HW * ABF;
    } else {
        int lvl = sel - 1;
        P = c_mact[lvl];
        I = (lvl == 0 ? f0 : lvl == 1 ? f1 : lvl == 2 ? f2 : f3) + (long)b * 256 * P;
        O = of + (long)b * VPIX * ABF + (long)c_vpix[lvl] * ABF;
    }
    const int p0 = tile0 * 32, c0 = blockIdx.y * 32;
    const int tx = threadIdx.x & 31, ty = threadIdx.x >> 5;
#pragma unroll
    for (int i = 0; i < 32; i += 8)
        t[ty + i][tx] = I[(long)(c0 + ty + i) * P + p0 + tx];
    __syncthreads();
#pragma unroll
    for (int i = 0; i < 32; i += 8) {
        __nv_bfloat16 h, l;
        split_bf(t[tx][ty + i], h, l);
        long e = (long)(p0 + ty + i) * ABF + c0 + tx;
        O[e] = h; O[e + 256] = l;
    }
}

// ---------------------------------------------------------------------------
// All weight prep in one launch.
// ---------------------------------------------------------------------------
#define SEG0 262144
#define SEG1 (SEG0 + 65536)
#define SEG2 (SEG1 + 884736)
#define SEG3 (SEG2 + 65536)
#define SEG4 (SEG3 + 384)
#define SEG5 (SEG4 + 256)

__global__ void prep_all(const float* __restrict__ qw, const float* __restrict__ vw,
                         const float* __restrict__ ow,
                         const float* __restrict__ offw, const float* __restrict__ attw,
                         const float* __restrict__ offb, const float* __restrict__ attb,
                         const float* __restrict__ bg, const float* __restrict__ bb,
                         const float* __restrict__ bm, const float* __restrict__ bv)
{
    long i = (long)blockIdx.x * 256 + threadIdx.x;
    if (i < SEG0) {
        long l = i >> 16, rem = i & 65535;
        long o = rem >> 8, c = rem & 255;
        __nv_bfloat16 h, lo;
        split_bf(vw[i], h, lo);
        long e = l * (256 * ABF) + o * ABF + c;
        g_vw[e] = h; g_vw[e + 256] = lo;
    } else if (i < SEG1) {
        long j = i - SEG0;
        long o = j >> 8, c = j & 255;
        __nv_bfloat16 h, lo;
        split_bf(ow[j], h, lo);
        g_ow[o * ABF + c] = h; g_ow[o * ABF + c + 256] = lo;
    } else if (i < SEG2) {
        long j = i - SEG1;
        long row = j >> 8, m = j & 255;
        long tap = row / 384, o = row - tap * 384;
        float v = (o < 256) ? offw[(o * 256 + m) * 9 + tap]
                            : attw[((o - 256) * 256 + m) * 9 + tap];
        __nv_bfloat16 h, lo;
        split_bf(v, h, lo);
        g_Woa[row * ABF + m] = h; g_Woa[row * ABF + m + 256] = lo;
    } else if (i < SEG3) {
        long j = i - SEG2;
        long c = j >> 8, m = j & 255;
        __nv_bfloat16 h, lo;
        split_bf(qw[m * 256 + c], h, lo);
        g_qwT[c * ABF + m] = h; g_qwT[c * ABF + m + 256] = lo;
    } else if (i < SEG4) {
        long j = i - SEG3;
        g_cb[j] = (j < 256) ? offb[j] : attb[j - 256];
    } else if (i < SEG5) {
        long j = i - SEG4;
        float s = bg[j] * rsqrtf(bv[j] + BN_EPS);
        g_bns[j] = s;
        g_bnb[j] = bb[j] - bm[j] * s;
    }
}

// ---------------------------------------------------------------------------
// Deformable sampling. One warp per (b, head, pixel). Split-bf16 output.
// ---------------------------------------------------------------------------
__global__ __launch_bounds__(256)
void sample_kernel()
{
    const int warp = threadIdx.x >> 5;
    const int lane = threadIdx.x & 31;
    const int pix  = blockIdx.x * 8 + warp;
    const int h    = blockIdx.y;
    const int b    = blockIdx.z;

    const int ph = pix >> 6;
    const int pw = pix & 63;
    const float refx = -1.f + 2.f * (float)pw / 63.f;
    const float refy = -1.f + 2.f * (float)ph / 63.f;

    const float* cvp = g_cv + ((long)b * HW + pix) * 384;
    float lg = -INFINITY, ox = 0.f, oy = 0.f;
    if (lane < 16) {
        lg = cvp[256 + h * 16 + lane];
        ox = tanhf(cvp[h * 32 + 2 * lane    ]) * 0.25f;
        oy = tanhf(cvp[h * 32 + 2 * lane + 1]) * 0.25f;
    }
    float mx = lg;
#pragma unroll
    for (int s = 16; s > 0; s >>= 1)
        mx = fmaxf(mx, __shfl_xor_sync(0xFFFFFFFFu, mx, s));
    float e = (lane < 16) ? expf(lg - mx) : 0.f;
    float sum = e;
#pragma unroll
    for (int s = 16; s > 0; s >>= 1)
        sum += __shfl_xor_sync(0xFFFFFFFFu, sum, s);
    float wgt = e / sum;

    const float* vb = g_v + (long)b * VSTRF + h * 32 + lane;

    float acc = 0.f;
#pragma unroll
    for (int i = 0; i < 16; i++) {
        const int lvl = i >> 2;
        const int sz  = 64 >> lvl;
        float aw = __shfl_sync(0xFFFFFFFFu, wgt, i);
        float gx = refx + __shfl_sync(0xFFFFFFFFu, ox, i);
        float gy = refy + __shfl_sync(0xFFFFFFFFu, oy, i);

        float xf = (gx + 1.f) * 0.5f * (float)(sz - 1);
        float yf = (gy + 1.f) * 0.5f * (float)(sz - 1);
        float x0f = floorf(xf), y0f = floorf(yf);
        int x0 = (int)x0f, y0 = (int)y0f;
        int x1 = x0 + 1,  y1 = y0 + 1;
        float wx1 = xf - x0f, wx0 = 1.f - wx1;
        float wy1 = yf - y0f, wy0 = 1.f - wy1;

        const float* vl = vb + c_voff[lvl];
        if (x0 >= 0 && x0 < sz && y0 >= 0 && y0 < sz)
            acc = fmaf(aw * wx0 * wy0, vl[(y0 * sz + x0) * 256], acc);
        if (x1 >= 0 && x1 < sz && y0 >= 0 && y0 < sz)
            acc = fmaf(aw * wx1 * wy0, vl[(y0 * sz + x1) * 256], acc);
        if (x0 >= 0 && x0 < sz && y1 >= 0 && y1 < sz)
            acc = fmaf(aw * wx0 * wy1, vl[(y1 * sz + x0) * 256], acc);
        if (x1 >= 0 && x1 < sz && y1 >= 0 && y1 < sz)
            acc = fmaf(aw * wx1 * wy1, vl[(y1 * sz + x1) * 256], acc);
    }

    __nv_bfloat16 hh, ll;
    split_bf(acc, hh, ll);
    long ebase = ((long)b * HW + pix) * ABF + h * 32 + lane;
    g_att[ebase] = hh; g_att[ebase + 256] = ll;
}

// ---------------------------------------------------------------------------
// Launch. Merged conv+vproj GEMM is the 4th launch (ncu capture slot).
// ---------------------------------------------------------------------------
extern "C" void kernel_launch(void* const* d_in, const int* in_sizes, int n_in,
                              void* d_out, int out_size)
{
    const float* query  = (const float*)d_in[0];
    const float* feat0  = (const float*)d_in[1];
    const float* feat1  = (const float*)d_in[2];
    const float* feat2  = (const float*)d_in[3];
    const float* feat3  = (const float*)d_in[4];
    const float* q_w    = (const float*)d_in[5];
    const float* v_w    = (const float*)d_in[6];
    const float* out_w  = (const float*)d_in[7];
    const float* off_w  = (const float*)d_in[8];
    const float* off_b  = (const float*)d_in[9];
    const float* attn_w = (const float*)d_in[10];
    const float* attn_b = (const float*)d_in[11];
    const float* bn_g   = (const float*)d_in[12];
    const float* bn_b   = (const float*)d_in[13];
    const float* bn_m   = (const float*)d_in[14];
    const float* bn_v   = (const float*)d_in[15];
    float* out = (float*)d_out;

    void* p;
    __nv_bfloat16 *gqT, *gfT;
    cudaGetSymbolAddress(&p, g_qT);  gqT  = (__nv_bfloat16*)p;
    cudaGetSymbolAddress(&p, g_fT);  gfT  = (__nv_bfloat16*)p;

    cudaFuncSetAttribute(mm_all, cudaFuncAttributeMaxDynamicSharedMemorySize, DSMEM_SZ);

    // 1. weight prep
    prep_all<<<(SEG5 + 255) / 256, 256>>>(q_w, v_w, out_w, off_w, attn_w,
                                          off_b, attn_b, bn_g, bn_b, bn_m, bn_v);
    // 2. all transposes (query + 4 levels)
    transposeAll<<<dim3(298, 8, BATCH), 256>>>(query, feat0, feat1, feat2, feat3,
                                               gqT, gfT);
    // 3. compose conv weights
    mm_all<<<dim3(27, 2, 1), 128, DSMEM_SZ>>>(0, nullptr, nullptr);

    // 4. merged conv + vproj GEMM   <-- ncu capture slot
    mm_all<<<dim3(182, 1, BATCH), 128, DSMEM_SZ>>>(1, nullptr, nullptr);

    // 5. deformable sampling
    sample_kernel<<<dim3(512, 8, BATCH), 256>>>();

    // 6. output projection + residual + BN + SiLU
    mm_all<<<dim3(32, 2, BATCH), 128, DSMEM_SZ>>>(3, query, out);
}

// round 10
// speedup vs baseline: 1.3770x; 1.3770x over previous
#include <cuda_runtime.h>
#include <cuda_bf16.h>
#include <math.h>
#include <stdint.h>

// ---------------------------------------------------------------------------
// Problem constants
// ---------------------------------------------------------------------------
#define BATCH   4
#define HW      4096
#define BN_EPS  1e-5f
#define VPIX    5440
#define VSTRF   (VPIX*256)
#define ABF     512                  // bf16 row: [256 hi][256 lo]

__device__ __constant__ int c_voff[4] = {0, 1048576, 1310720, 1376256};
__device__ __constant__ int c_vpix[4] = {0, 4096, 5120, 5376};
__device__ __constant__ int c_mact[4] = {4096, 1024, 256, 64};
__device__ __constant__ int c_vts[5]  = {0, 32, 40, 42, 43};
__device__ __constant__ int c_ftk[5]  = {0, 128, 160, 168, 170};   // feat transpose tiles
__constant__ float G4[4][3] = {{1.f,0.f,0.f},{0.5f,0.5f,0.5f},
                               {0.5f,-0.5f,0.5f},{0.f,0.f,1.f}};

// ---------------------------------------------------------------------------
// Scratch
// ---------------------------------------------------------------------------
__device__ __nv_bfloat16 g_fT [BATCH * VPIX * ABF];    // feats, channel-last split
__device__ __nv_bfloat16 g_att[BATCH * HW * ABF];      // sampler out, split
__device__ __nv_bfloat16 g_qwT[256 * ABF];             // q_w^T, B-format
__device__ __nv_bfloat16 g_vw [4 * 256 * ABF];         // v_w, B-format per level
__device__ __nv_bfloat16 g_ow [256 * ABF];             // out_w, B-format
__device__ __nv_bfloat16 g_W2 [16 * 384 * ABF];        // G-transformed raw conv w (A-format)
__device__ __nv_bfloat16 g_Uw [16 * 384 * ABF];        // winograd weights (B-format)
__device__ __nv_bfloat16 g_V  [16L * 4 * 1024 * ABF];  // winograd input transform
__device__ float g_M  [16L * 4 * 1024 * 384];          // winograd GEMM out
__device__ float g_v  [BATCH * VSTRF];                 // values fp32, channel-last
__device__ float g_cv [BATCH * HW * 384];              // conv out fp32 [pix][384]
__device__ float g_cb [384];
__device__ float g_bns[256], g_bnb[256];

// ---------------------------------------------------------------------------
// Helpers
// ---------------------------------------------------------------------------
__device__ __forceinline__ uint32_t smem_u32(const void* p) {
    uint32_t a;
    asm("{ .reg .u64 t; cvta.to.shared.u64 t, %1; cvt.u32.u64 %0, t; }"
        : "=r"(a) : "l"(p));
    return a;
}
__device__ __forceinline__ void cp16(uint32_t dst, const void* src, bool v) {
    int sz = v ? 16 : 0;
    asm volatile("cp.async.cg.shared.global [%0], [%1], 16, %2;\n"
                 :: "r"(dst), "l"(src), "r"(sz) : "memory");
}
__device__ __forceinline__ void cp_commit() {
    asm volatile("cp.async.commit_group;\n" ::: "memory");
}
__device__ __forceinline__ void cp_wait1() {
    asm volatile("cp.async.wait_group 1;\n" ::: "memory");
}
__device__ __forceinline__ void mma_bf16(float* c, const uint32_t* a, const uint32_t* b) {
    asm volatile(
        "mma.sync.aligned.m16n8k16.row.col.f32.bf16.bf16.f32 "
        "{%0,%1,%2,%3}, {%4,%5,%6,%7}, {%8,%9}, {%0,%1,%2,%3};"
        : "+f"(c[0]), "+f"(c[1]), "+f"(c[2]), "+f"(c[3])
        : "r"(a[0]), "r"(a[1]), "r"(a[2]), "r"(a[3]), "r"(b[0]), "r"(b[1]));
}
#define LDSM_X4(r0, r1, r2, r3, addr) \
    asm volatile("ldmatrix.sync.aligned.m8n8.x4.shared.b16 {%0,%1,%2,%3}, [%4];" \
        : "=r"(r0), "=r"(r1), "=r"(r2), "=r"(r3) : "r"(addr))

__device__ __forceinline__ void split_bf(float x, __nv_bfloat16& h, __nv_bfloat16& l) {
    h = __float2bfloat16(x);
    l = __float2bfloat16(x - __bfloat162float(h));
}

#define STG_B    16384
#define DSMEM_SZ (6 * STG_B)          // 96 KB -> 2 CTAs/SM

// ---------------------------------------------------------------------------
// Unified split-bf16 GEMM, all shapes K=256 (NK=8), D[128m][128n].
// lmode 0: compose U_t = W2_t . qw^T      (grid 48x2,   split-bf16 out)
// lmode 1: merged winograd-M + vproj      (grid 470,1,b)
// lmode 3: outproj (+resid, BN, SiLU)     (grid 32x2,b)
// 256 threads = 8 warps (2m x 4n), warp tile 64x32, 3-buffer cp.async ring,
// single barrier per stage.
// ---------------------------------------------------------------------------
__global__ __launch_bounds__(256, 2)
void mm_all(int lmode, const float* __restrict__ resid, float* __restrict__ outp)
{
    extern __shared__ float sm[];

    const int b    = blockIdx.z;
    const int tid  = threadIdx.x;
    const int wid  = tid >> 5;
    const int lane = tid & 31;
    const int wm   = wid >> 2;
    const int wn   = wid & 3;
    const int gid  = lane >> 2;
    const int tig  = lane & 3;
    const int l8   = lane & 7;
    const int lm   = (lane >> 3) & 1;
    const int lh   = lane >> 4;

    // ---- per-CTA mode & geometry ----
    int mode, m0, n0, lvl = 0, M_act = 1 << 30;
    long mBase = 0;
    const __nv_bfloat16 *Abase, *Bbase;
    if (lmode == 1) {
        int idx = blockIdx.x;
        if (idx < 384) {
            mode = 1;
            int t = idx / 24, sub = idx % 24;
            m0 = (sub & 7) * 128; n0 = (sub >> 3) * 128;
            Abase = g_V + ((long)(t * 4 + b) * 1024) * ABF;
            Bbase = g_Uw + (long)t * 384 * ABF;
            mBase = ((long)(t * 4 + b) * 1024) * 384;
            M_act = 1024;
        } else {
            mode = 2; int tv = idx - 384;
            int nt = (tv >= 43) ? 1 : 0;
            int mtile = tv - nt * 43;
            while (mtile >= c_vts[lvl + 1]) lvl++;
            m0 = (mtile - c_vts[lvl]) * 128;
            n0 = nt * 128;
            M_act = c_mact[lvl];
            Abase = g_fT + (long)b * VPIX * ABF + (long)c_vpix[lvl] * ABF;
            Bbase = g_vw + lvl * 256 * ABF;
        }
    } else if (lmode == 0) {
        mode = 0; m0 = blockIdx.x * 128; n0 = blockIdx.y * 128;
        Abase = g_W2; Bbase = g_qwT;
        M_act = 6144;
    } else {
        mode = 3; m0 = blockIdx.x * 128; n0 = blockIdx.y * 128;
        Abase = g_att + (long)b * HW * ABF; Bbase = g_ow;
        M_act = 4096;
    }

    // ---- hoisted loader state ----
    const int r0    = tid >> 3;         // 0..31, rows r0 + 32i
    const int sub   = tid & 7;
    const int plane = sub >> 2;
    const int kc    = sub & 3;
    const int phys  = sub ^ (r0 & 7);
    const uint32_t smb = smem_u32(sm);

    const __nv_bfloat16* aB = Abase + (long)(m0 + r0) * ABF + plane * 256 + kc * 8;
    const __nv_bfloat16* bP = Bbase + (long)(n0 + r0) * ABF + plane * 256 + kc * 8;
    const uint32_t dA0 = smb + r0 * 128 + phys * 16;
    const uint32_t dB0 = dA0 + 3 * STG_B;

    bool aOK[4];
#pragma unroll
    for (int i = 0; i < 4; i++) aOK[i] = (m0 + r0 + 32 * i) < M_act;

    float acc[4][4][4];
#pragma unroll
    for (int mt = 0; mt < 4; mt++)
#pragma unroll
        for (int nt = 0; nt < 4; nt++)
#pragma unroll
            for (int r = 0; r < 4; r++) acc[mt][nt][r] = 0.f;

    auto load_stage = [&](int s, int buf) {
        const __nv_bfloat16* ap = aB + s * 32;
        const __nv_bfloat16* bp = bP + s * 32;
        const uint32_t dA = dA0 + buf * STG_B;
        const uint32_t dB = dB0 + buf * STG_B;
#pragma unroll
        for (int i = 0; i < 4; i++) {
            cp16(dA + i * 4096, aOK[i] ? (ap + i * 32 * ABF) : (const void*)Abase, aOK[i]);
            cp16(dB + i * 4096, bp + i * 32 * ABF, true);
        }
    };

    load_stage(0, 0); cp_commit();
    load_stage(1, 1); cp_commit();

    for (int s = 0; s < 8; s++) {
        const int buf = s % 3;
        cp_wait1();
        __syncthreads();
        if (s + 2 < 8) { load_stage(s + 2, (s + 2) % 3); }
        cp_commit();

        const uint32_t aBase_s = smb + buf * STG_B;
        const uint32_t bBase_s = smb + (3 + buf) * STG_B;
#pragma unroll
        for (int kk = 0; kk < 2; kk++) {
            const int chH = kk * 2 + lh;
            const int chL = chH + 4;
            uint32_t ah[4][4], al[4][4], bh[4][2], bl[4][2];
#pragma unroll
            for (int mt = 0; mt < 4; mt++) {
                int row = wm * 64 + mt * 16 + l8 + lm * 8;
                uint32_t base = aBase_s + row * 128;
                LDSM_X4(ah[mt][0], ah[mt][1], ah[mt][2], ah[mt][3],
                        base + ((chH ^ l8) << 4));
                LDSM_X4(al[mt][0], al[mt][1], al[mt][2], al[mt][3],
                        base + ((chL ^ l8) << 4));
            }
#pragma unroll
            for (int np = 0; np < 2; np++) {
                int row = wn * 32 + np * 16 + l8 + lm * 8;
                uint32_t base = bBase_s + row * 128;
                LDSM_X4(bh[2 * np][0], bh[2 * np + 1][0],
                        bh[2 * np][1], bh[2 * np + 1][1],
                        base + ((chH ^ l8) << 4));
                LDSM_X4(bl[2 * np][0], bl[2 * np + 1][0],
                        bl[2 * np][1], bl[2 * np + 1][1],
                        base + ((chL ^ l8) << 4));
            }
#pragma unroll
            for (int mt = 0; mt < 4; mt++)
#pragma unroll
                for (int nt = 0; nt < 4; nt++) {
                    mma_bf16(acc[mt][nt], ah[mt], bh[nt]);
                    mma_bf16(acc[mt][nt], ah[mt], bl[nt]);
                    mma_bf16(acc[mt][nt], al[mt], bh[nt]);
                }
        }
    }

    // ---- epilogues ----
#pragma unroll
    for (int mt = 0; mt < 4; mt++) {
        int r0e = m0 + wm * 64 + mt * 16 + gid;
#pragma unroll
        for (int nt = 0; nt < 4; nt++) {
            int col = n0 + wn * 32 + nt * 8 + tig * 2;
#pragma unroll
            for (int h = 0; h < 2; h++) {
                int r = r0e + h * 8;
                float vx = acc[mt][nt][2 * h];
                float vy = acc[mt][nt][2 * h + 1];
                if (mode == 0) {
                    long e = (long)r * ABF + col;
                    __nv_bfloat16 hh, ll;
                    split_bf(vx, hh, ll); g_Uw[e]     = hh; g_Uw[e + 256]     = ll;
                    split_bf(vy, hh, ll); g_Uw[e + 1] = hh; g_Uw[e + 1 + 256] = ll;
                } else if (mode == 1) {
                    *(float2*)&g_M[mBase + (long)r * 384 + col] = make_float2(vx, vy);
                } else if (mode == 2) {
                    if (r < M_act) {
                        long row = c_vpix[lvl] + r;
                        *(float2*)&g_v[(long)b * VSTRF + row * 256 + col] =
                            make_float2(vx, vy);
                    }
                } else {
                    const float* qb = resid + (long)b * 256 * HW;
                    float* yb = outp + (long)b * 256 * HW;
#pragma unroll
                    for (int j = 0; j < 2; j++) {
                        int oc = col + j;
                        float x  = ((j == 0) ? vx : vy) + qb[(long)oc * HW + r];
                        float xn = x * g_bns[oc] + g_bnb[oc];
                        yb[(long)oc * HW + r] = xn / (1.f + expf(-xn));
                    }
                }
            }
        }
    }
}

// ---------------------------------------------------------------------------
// Merged: feat transposes (x<170) + winograd input transform (x>=170).
// ---------------------------------------------------------------------------
__global__ __launch_bounds__(256)
void prepActs(const float* __restrict__ q,
              const float* __restrict__ f0, const float* __restrict__ f1,
              const float* __restrict__ f2, const float* __restrict__ f3)
{
    __shared__ float tbuf[32][33];
    __shared__ float s[4][18][32];
    const int b = blockIdx.z;
    const int tid = threadIdx.x;

    if (blockIdx.x < 170) {
        int lvl = 0;
        while ((int)blockIdx.x >= c_ftk[lvl + 1]) lvl++;
        const int P  = c_mact[lvl];
        const int p0 = (blockIdx.x - c_ftk[lvl]) * 32;
        const float* I = (lvl == 0 ? f0 : lvl == 1 ? f1 : lvl == 2 ? f2 : f3)
                       + (long)b * 256 * P;
        __nv_bfloat16* Of = g_fT + (long)b * VPIX * ABF + (long)c_vpix[lvl] * ABF;
        const int c0 = blockIdx.y * 32;
        const int tx = tid & 31, ty = tid >> 5;
#pragma unroll
        for (int i = 0; i < 32; i += 8)
            tbuf[ty + i][tx] = I[(long)(c0 + ty + i) * P + p0 + tx];
        __syncthreads();
#pragma unroll
        for (int i = 0; i < 32; i += 8) {
            __nv_bfloat16 h, l;
            split_bf(tbuf[tx][ty + i], h, l);
            long e = (long)(p0 + ty + i) * ABF + c0 + tx;
            Of[e] = h; Of[e + 256] = l;
        }
    } else {
        const int e   = blockIdx.x - 170;   // 0..127
        const int txg = e & 3, tyr = e >> 2;
        const int cg  = blockIdx.y;         // 0..7
        for (int idx = tid; idx < 2304; idx += 256) {
            int cc  = idx / 72;
            int rem = idx - cc * 72;
            int row = rem / 18;
            int col = rem - row * 18;
            int gy = 2 * tyr - 1 + row;
            int gx = txg * 16 - 1 + col;
            float v = 0.f;
            if (gy >= 0 && gy < 64 && gx >= 0 && gx < 64)
                v = q[((long)b * 256 + cg * 32 + cc) * 4096 + gy * 64 + gx];
            s[row][col][cc] = v;
        }
        __syncthreads();
        const int lane = tid & 31, tx = tid >> 5;   // 8 warps = 8 tiles
        float d[4][4];
#pragma unroll
        for (int i = 0; i < 4; i++)
#pragma unroll
            for (int j = 0; j < 4; j++) d[i][j] = s[i][2 * tx + j][lane];
        float t1[4][4];
#pragma unroll
        for (int j = 0; j < 4; j++) {
            t1[0][j] = d[0][j] - d[2][j];
            t1[1][j] = d[1][j] + d[2][j];
            t1[2][j] = d[2][j] - d[1][j];
            t1[3][j] = d[1][j] - d[3][j];
        }
        float V[4][4];
#pragma unroll
        for (int i = 0; i < 4; i++) {
            V[i][0] = t1[i][0] - t1[i][2];
            V[i][1] = t1[i][1] + t1[i][2];
            V[i][2] = t1[i][2] - t1[i][1];
            V[i][3] = t1[i][1] - t1[i][3];
        }
        const int tile = tyr * 32 + txg * 8 + tx;
#pragma unroll
        for (int i = 0; i < 4; i++)
#pragma unroll
            for (int j = 0; j < 4; j++) {
                int t = i * 4 + j;
                __nv_bfloat16 h, l;
                split_bf(V[i][j], h, l);
                long base = ((long)(t * 4 + b) * 1024 + tile) * ABF + cg * 32 + lane;
                g_V[base] = h; g_V[base + 256] = l;
            }
    }
}

// ---------------------------------------------------------------------------
// Winograd output transform: Y = A^T M A + bias -> g_cv [pix][384]
// ---------------------------------------------------------------------------
__global__ __launch_bounds__(192)
void wgOut()
{
    const int tile = blockIdx.x;
    const int oc   = blockIdx.y * 192 + threadIdx.x;
    const int b    = blockIdx.z;
    const long tstr = (long)4 * 1024 * 384;
    const long base = ((long)b * 1024 + tile) * 384 + oc;
    float m[4][4];
#pragma unroll
    for (int t = 0; t < 16; t++)
        m[t >> 2][t & 3] = g_M[(long)t * tstr + base];
    float tmp[2][4];
#pragma unroll
    for (int j = 0; j < 4; j++) {
        tmp[0][j] = m[0][j] + m[1][j] + m[2][j];
        tmp[1][j] = m[1][j] - m[2][j] - m[3][j];
    }
    const int ty = tile >> 5, tx = tile & 31;
    const float bs = g_cb[oc];
#pragma unroll
    for (int i = 0; i < 2; i++) {
        float y0 = tmp[i][0] + tmp[i][1] + tmp[i][2] + bs;
        float y1 = tmp[i][1] - tmp[i][2] - tmp[i][3] + bs;
        long prow = (long)b * 4096 + (2 * ty + i) * 64 + 2 * tx;
        g_cv[prow * 384 + oc]       = y0;
        g_cv[(prow + 1) * 384 + oc] = y1;
    }
}

// ---------------------------------------------------------------------------
// Weight prep (one launch): vw, ow, qwT, G-transformed conv weights, bias, bn.
// ---------------------------------------------------------------------------
#define S0 262144
#define S1 (S0 + 65536)
#define S2 (S1 + 65536)
#define S3 (S2 + 1572864)
#define S4 (S3 + 384)
#define S5 (S4 + 256)

__global__ void prep_all(const float* __restrict__ qw, const float* __restrict__ vw,
                         const float* __restrict__ ow,
                         const float* __restrict__ offw, const float* __restrict__ attw,
                         const float* __restrict__ offb, const float* __restrict__ attb,
                         const float* __restrict__ bg, const float* __restrict__ bb,
                         const float* __restrict__ bm, const float* __restrict__ bv)
{
    long i = (long)blockIdx.x * 256 + threadIdx.x;
    if (i < S0) {
        long l = i >> 16, rem = i & 65535;
        long o = rem >> 8, c = rem & 255;
        __nv_bfloat16 h, lo;
        split_bf(vw[i], h, lo);
        long e = l * (256 * ABF) + o * ABF + c;
        g_vw[e] = h; g_vw[e + 256] = lo;
    } else if (i < S1) {
        long j = i - S0;
        long o = j >> 8, c = j & 255;
        __nv_bfloat16 h, lo;
        split_bf(ow[j], h, lo);
        g_ow[o * ABF + c] = h; g_ow[o * ABF + c + 256] = lo;
    } else if (i < S2) {
        long j = i - S1;
        long c = j >> 8, m = j & 255;
        __nv_bfloat16 h, lo;
        split_bf(qw[m * 256 + c], h, lo);
        g_qwT[c * ABF + m] = h; g_qwT[c * ABF + m + 256] = lo;
    } else if (i < S3) {
        long j = i - S2;
        int t = (int)(j / 98304);
        int rem = (int)(j - (long)t * 98304);
        int o = rem >> 8, m = rem & 255;
        int ti = t >> 2, tj = t & 3;
        const float* wsrc = (o < 256) ? offw + ((long)o * 256 + m) * 9
                                      : attw + ((long)(o - 256) * 256 + m) * 9;
        float acc = 0.f;
#pragma unroll
        for (int ki = 0; ki < 3; ki++)
#pragma unroll
            for (int kj = 0; kj < 3; kj++)
                acc += G4[ti][ki] * G4[tj][kj] * wsrc[ki * 3 + kj];
        __nv_bfloat16 h, lo;
        split_bf(acc, h, lo);
        long e = ((long)t * 384 + o) * ABF + m;
        g_W2[e] = h; g_W2[e + 256] = lo;
    } else if (i < S4) {
        long j = i - S3;
        g_cb[j] = (j < 256) ? offb[j] : attb[j - 256];
    } else if (i < S5) {
        long j = i - S4;
        float sc = bg[j] * rsqrtf(bv[j] + BN_EPS);
        g_bns[j] = sc;
        g_bnb[j] = bb[j] - bm[j] * sc;
    }
}

// ---------------------------------------------------------------------------
// Deformable sampling. One warp per (b, head, pixel). Split-bf16 output.
// ---------------------------------------------------------------------------
__global__ __launch_bounds__(256)
void sample_kernel()
{
    const int warp = threadIdx.x >> 5;
    const int lane = threadIdx.x & 31;
    const int pix  = blockIdx.x * 8 + warp;
    const int h    = blockIdx.y;
    const int b    = blockIdx.z;

    const int ph = pix >> 6;
    const int pw = pix & 63;
    const float refx = -1.f + 2.f * (float)pw / 63.f;
    const float refy = -1.f + 2.f * (float)ph / 63.f;

    const float* cvp = g_cv + ((long)b * HW + pix) * 384;
    float lg = -INFINITY, ox = 0.f, oy = 0.f;
    if (lane < 16) {
        lg = cvp[256 + h * 16 + lane];
        ox = tanhf(cvp[h * 32 + 2 * lane    ]) * 0.25f;
        oy = tanhf(cvp[h * 32 + 2 * lane + 1]) * 0.25f;
    }
    float mx = lg;
#pragma unroll
    for (int s = 16; s > 0; s >>= 1)
        mx = fmaxf(mx, __shfl_xor_sync(0xFFFFFFFFu, mx, s));
    float e = (lane < 16) ? expf(lg - mx) : 0.f;
    float sum = e;
#pragma unroll
    for (int s = 16; s > 0; s >>= 1)
        sum += __shfl_xor_sync(0xFFFFFFFFu, sum, s);
    float wgt = e / sum;

    const float* vb = g_v + (long)b * VSTRF + h * 32 + lane;

    float acc = 0.f;
#pragma unroll
    for (int i = 0; i < 16; i++) {
        const int lvl = i >> 2;
        const int sz  = 64 >> lvl;
        float aw = __shfl_sync(0xFFFFFFFFu, wgt, i);
        float gx = refx + __shfl_sync(0xFFFFFFFFu, ox, i);
        float gy = refy + __shfl_sync(0xFFFFFFFFu, oy, i);

        float xf = (gx + 1.f) * 0.5f * (float)(sz - 1);
        float yf = (gy + 1.f) * 0.5f * (float)(sz - 1);
        float x0f = floorf(xf), y0f = floorf(yf);
        int x0 = (int)x0f, y0 = (int)y0f;
        int x1 = x0 + 1,  y1 = y0 + 1;
        float wx1 = xf - x0f, wx0 = 1.f - wx1;
        float wy1 = yf - y0f, wy0 = 1.f - wy1;

        const float* vl = vb + c_voff[lvl];
        if (x0 >= 0 && x0 < sz && y0 >= 0 && y0 < sz)
            acc = fmaf(aw * wx0 * wy0, vl[(y0 * sz + x0) * 256], acc);
        if (x1 >= 0 && x1 < sz && y0 >= 0 && y0 < sz)
            acc = fmaf(aw * wx1 * wy0, vl[(y0 * sz + x1) * 256], acc);
        if (x0 >= 0 && x0 < sz && y1 >= 0 && y1 < sz)
            acc = fmaf(aw * wx0 * wy1, vl[(y1 * sz + x0) * 256], acc);
        if (x1 >= 0 && x1 < sz && y1 >= 0 && y1 < sz)
            acc = fmaf(aw * wx1 * wy1, vl[(y1 * sz + x1) * 256], acc);
    }

    __nv_bfloat16 hh, ll;
    split_bf(acc, hh, ll);
    long ebase = ((long)b * HW + pix) * ABF + h * 32 + lane;
    g_att[ebase] = hh; g_att[ebase + 256] = ll;
}

// ---------------------------------------------------------------------------
// Launch. Main GEMM (winograd + vproj) is the 4th launch (ncu capture slot).
// ---------------------------------------------------------------------------
extern "C" void kernel_launch(void* const* d_in, const int* in_sizes, int n_in,
                              void* d_out, int out_size)
{
    const float* query  = (const float*)d_in[0];
    const float* feat0  = (const float*)d_in[1];
    const float* feat1  = (const float*)d_in[2];
    const float* feat2  = (const float*)d_in[3];
    const float* feat3  = (const float*)d_in[4];
    const float* q_w    = (const float*)d_in[5];
    const float* v_w    = (const float*)d_in[6];
    const float* out_w  = (const float*)d_in[7];
    const float* off_w  = (const float*)d_in[8];
    const float* off_b  = (const float*)d_in[9];
    const float* attn_w = (const float*)d_in[10];
    const float* attn_b = (const float*)d_in[11];
    const float* bn_g   = (const float*)d_in[12];
    const float* bn_b   = (const float*)d_in[13];
    const float* bn_m   = (const float*)d_in[14];
    const float* bn_v   = (const float*)d_in[15];
    float* out = (float*)d_out;

    cudaFuncSetAttribute(mm_all, cudaFuncAttributeMaxDynamicSharedMemorySize, DSMEM_SZ);

    // 1. weight prep (incl. G-transform of raw conv weights)
    prep_all<<<(S5 + 255) / 256, 256>>>(q_w, v_w, out_w, off_w, attn_w,
                                        off_b, attn_b, bn_g, bn_b, bn_m, bn_v);
    // 2. feat transposes + winograd input transform of query
    prepActs<<<dim3(298, 8, BATCH), 256>>>(query, feat0, feat1, feat2, feat3);

    // 3. compose winograd weights: U_t = W2_t . qw^T
    mm_all<<<dim3(48, 2, 1), 256, DSMEM_SZ>>>(0, nullptr, nullptr);

    // 4. merged winograd-M + vproj GEMM   <-- ncu capture slot
    mm_all<<<dim3(470, 1, BATCH), 256, DSMEM_SZ>>>(1, nullptr, nullptr);

    // 5. winograd output transform (+conv bias) -> g_cv
    wgOut<<<dim3(1024, 2, BATCH), 192>>>();

    // 6. deformable sampling
    sample_kernel<<<dim3(512, 8, BATCH), 256>>>();

    // 7. output projection + residual + BN + SiLU
    mm_all<<<dim3(32, 2, BATCH), 256, DSMEM_SZ>>>(3, query, out);
}

// round 11
// speedup vs baseline: 1.6080x; 1.1678x over previous
#include <cuda_runtime.h>
#include <cuda_fp16.h>
#include <math.h>
#include <stdint.h>

// ---------------------------------------------------------------------------
// Problem constants
// ---------------------------------------------------------------------------
#define BATCH   4
#define HW      4096
#define BN_EPS  1e-5f
#define VPIX    5440
#define VSTRF   (VPIX*256)
#define WROW    512                  // weight row: [256 hi][256 lo] fp16
#define AROW    256                  // activation row: 256 fp16 (hi only)

__device__ __constant__ int c_voff[4] = {0, 1048576, 1310720, 1376256};
__device__ __constant__ int c_vpix[4] = {0, 4096, 5120, 5376};
__device__ __constant__ int c_mact[4] = {4096, 1024, 256, 64};
__device__ __constant__ int c_vts[5]  = {0, 32, 40, 42, 43};
__device__ __constant__ int c_ftk[5]  = {0, 128, 160, 168, 170};
__constant__ float G4[4][3] = {{1.f,0.f,0.f},{0.5f,0.5f,0.5f},
                               {0.5f,-0.5f,0.5f},{0.f,0.f,1.f}};

// ---------------------------------------------------------------------------
// Scratch
// ---------------------------------------------------------------------------
__device__ __half g_fT [BATCH * VPIX * AROW];      // feats, channel-last fp16
__device__ __half g_att[BATCH * HW * AROW];        // sampler out fp16
__device__ __half g_qwT[256 * WROW];               // q_w^T, split (B fmt)
__device__ __half g_vw [4 * 256 * WROW];           // v_w, split (B fmt)
__device__ __half g_ow [256 * WROW];               // out_w, split (B fmt)
__device__ __half g_W2 [16 * 384 * WROW];          // G-transformed conv w, split (A fmt)
__device__ __half g_Uw [16 * 384 * WROW];          // winograd weights, split (B fmt)
__device__ __half g_V  [16L * 4 * 1024 * AROW];    // winograd input transform fp16
__device__ float g_M  [16L * 4 * 1024 * 384];      // winograd GEMM out fp32
__device__ float g_v  [BATCH * VSTRF];             // values fp32 channel-last
__device__ float g_cb [384];
__device__ float g_bns[256], g_bnb[256];

// ---------------------------------------------------------------------------
// Helpers
// ---------------------------------------------------------------------------
__device__ __forceinline__ uint32_t smem_u32(const void* p) {
    uint32_t a;
    asm("{ .reg .u64 t; cvta.to.shared.u64 t, %1; cvt.u32.u64 %0, t; }"
        : "=r"(a) : "l"(p));
    return a;
}
__device__ __forceinline__ void cp16(uint32_t dst, const void* src, bool v) {
    int sz = v ? 16 : 0;
    asm volatile("cp.async.cg.shared.global [%0], [%1], 16, %2;\n"
                 :: "r"(dst), "l"(src), "r"(sz) : "memory");
}
__device__ __forceinline__ void cp_commit() {
    asm volatile("cp.async.commit_group;\n" ::: "memory");
}
__device__ __forceinline__ void cp_wait1() {
    asm volatile("cp.async.wait_group 1;\n" ::: "memory");
}
__device__ __forceinline__ void mma_f16(float* c, const uint32_t* a, const uint32_t* b) {
    asm volatile(
        "mma.sync.aligned.m16n8k16.row.col.f32.f16.f16.f32 "
        "{%0,%1,%2,%3}, {%4,%5,%6,%7}, {%8,%9}, {%0,%1,%2,%3};"
        : "+f"(c[0]), "+f"(c[1]), "+f"(c[2]), "+f"(c[3])
        : "r"(a[0]), "r"(a[1]), "r"(a[2]), "r"(a[3]), "r"(b[0]), "r"(b[1]));
}
#define LDSM_X4(r0, r1, r2, r3, addr) \
    asm volatile("ldmatrix.sync.aligned.m8n8.x4.shared.b16 {%0,%1,%2,%3}, [%4];" \
        : "=r"(r0), "=r"(r1), "=r"(r2), "=r"(r3) : "r"(addr))

__device__ __forceinline__ void split_h(float x, __half& h, __half& l) {
    h = __float2half_rn(x);
    l = __float2half_rn(x - __half2float(h));
}

#define STG_B    16384
#define DSMEM_SZ (6 * STG_B)          // 96 KB -> 2 CTAs/SM

// ---------------------------------------------------------------------------
// Unified fp16 GEMM, K=256 (NK=8), D[128m][128n] = sum_k A[m][k]*B[n][k].
// LM 0: compose  (A = g_W2 SPLIT, 3-term; out split g_Uw)
// LM 1: merged winograd-M + vproj (A fp16 hi-only, 2-term)
// LM 3: outproj (+resid, BN, SiLU)  (A fp16 hi-only, 2-term)
// 256 threads = 8 warps (2m x 4n), warp tile 64x32, 3-buffer cp.async ring.
// ---------------------------------------------------------------------------
template<int LM>
__global__ __launch_bounds__(256, 2)
void mm_all(const float* __restrict__ resid, float* __restrict__ outp)
{
    constexpr bool SPLIT_A = (LM == 0);
    extern __shared__ float sm[];

    const int b    = blockIdx.z;
    const int tid  = threadIdx.x;
    const int wid  = tid >> 5;
    const int lane = tid & 31;
    const int wm   = wid >> 2;
    const int wn   = wid & 3;
    const int gid  = lane >> 2;
    const int tig  = lane & 3;
    const int l8   = lane & 7;
    const int lm   = (lane >> 3) & 1;
    const int lh   = lane >> 4;

    // ---- per-CTA mode & geometry ----
    int mode, m0, n0, lvl = 0, M_act = 1 << 30;
    long mBase = 0;
    const __half *Abase, *Bbase;
    if (LM == 1) {
        int idx = blockIdx.x;
        if (idx < 384) {
            mode = 1;
            int t = idx / 24, sub = idx % 24;
            m0 = (sub & 7) * 128; n0 = (sub >> 3) * 128;
            Abase = g_V + ((long)(t * 4 + b) * 1024) * AROW;
            Bbase = g_Uw + (long)t * 384 * WROW;
            mBase = ((long)(t * 4 + b) * 1024) * 384;
            M_act = 1024;
        } else {
            mode = 2; int tv = idx - 384;
            int nt = (tv >= 43) ? 1 : 0;
            int mtile = tv - nt * 43;
            while (mtile >= c_vts[lvl + 1]) lvl++;
            m0 = (mtile - c_vts[lvl]) * 128;
            n0 = nt * 128;
            M_act = c_mact[lvl];
            Abase = g_fT + (long)b * VPIX * AROW + (long)c_vpix[lvl] * AROW;
            Bbase = g_vw + lvl * 256 * WROW;
        }
    } else if (LM == 0) {
        mode = 0; m0 = blockIdx.x * 128; n0 = blockIdx.y * 128;
        Abase = g_W2; Bbase = g_qwT;
        M_act = 6144;
    } else {
        mode = 3; m0 = blockIdx.x * 128; n0 = blockIdx.y * 128;
        Abase = g_att + (long)b * HW * AROW; Bbase = g_ow;
        M_act = 4096;
    }

    // ---- hoisted loader state ----
    const int r0    = tid >> 3;         // 0..31, rows r0 + 32i
    const int sub   = tid & 7;
    const int plane = sub >> 2;
    const int kc    = sub & 3;
    const int phys  = sub ^ (r0 & 7);
    const uint32_t smb = smem_u32(sm);

    const __half* aB = SPLIT_A
        ? (Abase + (long)(m0 + r0) * WROW + plane * 256 + kc * 8)
        : (Abase + (long)(m0 + r0) * AROW + sub * 8);      // sub<4 used
    const __half* bP = Bbase + (long)(n0 + r0) * WROW + plane * 256 + kc * 8;
    const uint32_t dA0 = smb + r0 * 128 + phys * 16;
    const uint32_t dB0 = dA0 + 3 * STG_B;

    bool aOK[4];
#pragma unroll
    for (int i = 0; i < 4; i++) aOK[i] = (m0 + r0 + 32 * i) < M_act;

    float acc[4][4][4];
#pragma unroll
    for (int mt = 0; mt < 4; mt++)
#pragma unroll
        for (int nt = 0; nt < 4; nt++)
#pragma unroll
            for (int r = 0; r < 4; r++) acc[mt][nt][r] = 0.f;

    auto load_stage = [&](int s, int buf) {
        const __half* bp = bP + s * 32;
        const uint32_t dB = dB0 + buf * STG_B;
#pragma unroll
        for (int i = 0; i < 4; i++)
            cp16(dB + i * 4096, bp + i * 32 * WROW, true);
        const uint32_t dA = dA0 + buf * STG_B;
        if (SPLIT_A) {
            const __half* ap = aB + s * 32;
#pragma unroll
            for (int i = 0; i < 4; i++)
                cp16(dA + i * 4096, aOK[i] ? (ap + i * 32 * WROW) : (const void*)Abase, aOK[i]);
        } else if (sub < 4) {
            const __half* ap = aB + s * 32;
#pragma unroll
            for (int i = 0; i < 4; i++)
                cp16(dA + i * 4096, aOK[i] ? (ap + i * 32 * AROW) : (const void*)Abase, aOK[i]);
        }
    };

    load_stage(0, 0); cp_commit();
    load_stage(1, 1); cp_commit();

    for (int s = 0; s < 8; s++) {
        const int buf = s % 3;
        cp_wait1();
        __syncthreads();
        if (s + 2 < 8) { load_stage(s + 2, (s + 2) % 3); }
        cp_commit();

        const uint32_t aBase_s = smb + buf * STG_B;
        const uint32_t bBase_s = smb + (3 + buf) * STG_B;
#pragma unroll
        for (int kk = 0; kk < 2; kk++) {
            const int chH = kk * 2 + lh;       // 0..3
            const int chL = chH + 4;
            uint32_t ah[4][4], al[4][4], bh[4][2], bl[4][2];
#pragma unroll
            for (int mt = 0; mt < 4; mt++) {
                int row = wm * 64 + mt * 16 + l8 + lm * 8;
                uint32_t base = aBase_s + row * 128;
                LDSM_X4(ah[mt][0], ah[mt][1], ah[mt][2], ah[mt][3],
                        base + ((chH ^ l8) << 4));
                if (SPLIT_A)
                    LDSM_X4(al[mt][0], al[mt][1], al[mt][2], al[mt][3],
                            base + ((chL ^ l8) << 4));
            }
#pragma unroll
            for (int np = 0; np < 2; np++) {
                int row = wn * 32 + np * 16 + l8 + lm * 8;
                uint32_t base = bBase_s + row * 128;
                LDSM_X4(bh[2 * np][0], bh[2 * np + 1][0],
                        bh[2 * np][1], bh[2 * np + 1][1],
                        base + ((chH ^ l8) << 4));
                LDSM_X4(bl[2 * np][0], bl[2 * np + 1][0],
                        bl[2 * np][1], bl[2 * np + 1][1],
                        base + ((chL ^ l8) << 4));
            }
#pragma unroll
            for (int mt = 0; mt < 4; mt++)
#pragma unroll
                for (int nt = 0; nt < 4; nt++) {
                    mma_f16(acc[mt][nt], ah[mt], bh[nt]);
                    mma_f16(acc[mt][nt], ah[mt], bl[nt]);
                    if (SPLIT_A) mma_f16(acc[mt][nt], al[mt], bh[nt]);
                }
        }
    }

    // ---- epilogues ----
#pragma unroll
    for (int mt = 0; mt < 4; mt++) {
        int r0e = m0 + wm * 64 + mt * 16 + gid;
#pragma unroll
        for (int nt = 0; nt < 4; nt++) {
            int col = n0 + wn * 32 + nt * 8 + tig * 2;
#pragma unroll
            for (int h = 0; h < 2; h++) {
                int r = r0e + h * 8;
                float vx = acc[mt][nt][2 * h];
                float vy = acc[mt][nt][2 * h + 1];
                if (mode == 0) {
                    long e = (long)r * WROW + col;
                    __half hh, ll;
                    split_h(vx, hh, ll); g_Uw[e]     = hh; g_Uw[e + 256]     = ll;
                    split_h(vy, hh, ll); g_Uw[e + 1] = hh; g_Uw[e + 1 + 256] = ll;
                } else if (mode == 1) {
                    *(float2*)&g_M[mBase + (long)r * 384 + col] = make_float2(vx, vy);
                } else if (mode == 2) {
                    if (r < M_act) {
                        long row = c_vpix[lvl] + r;
                        *(float2*)&g_v[(long)b * VSTRF + row * 256 + col] =
                            make_float2(vx, vy);
                    }
                } else {
                    const float* qb = resid + (long)b * 256 * HW;
                    float* yb = outp + (long)b * 256 * HW;
#pragma unroll
                    for (int j = 0; j < 2; j++) {
                        int oc = col + j;
                        float x  = ((j == 0) ? vx : vy) + qb[(long)oc * HW + r];
                        float xn = x * g_bns[oc] + g_bnb[oc];
                        yb[(long)oc * HW + r] = xn / (1.f + expf(-xn));
                    }
                }
            }
        }
    }
}

// ---------------------------------------------------------------------------
// Merged: feat transposes (x<170) + winograd input transform (x>=170).
// ---------------------------------------------------------------------------
__global__ __launch_bounds__(256)
void prepActs(const float* __restrict__ q,
              const float* __restrict__ f0, const float* __restrict__ f1,
              const float* __restrict__ f2, const float* __restrict__ f3)
{
    __shared__ float tbuf[32][33];
    __shared__ float s[4][18][32];
    const int b = blockIdx.z;
    const int tid = threadIdx.x;

    if (blockIdx.x < 170) {
        int lvl = 0;
        while ((int)blockIdx.x >= c_ftk[lvl + 1]) lvl++;
        const int P  = c_mact[lvl];
        const int p0 = (blockIdx.x - c_ftk[lvl]) * 32;
        const float* I = (lvl == 0 ? f0 : lvl == 1 ? f1 : lvl == 2 ? f2 : f3)
                       + (long)b * 256 * P;
        __half* Of = g_fT + (long)b * VPIX * AROW + (long)c_vpix[lvl] * AROW;
        const int c0 = blockIdx.y * 32;
        const int tx = tid & 31, ty = tid >> 5;
#pragma unroll
        for (int i = 0; i < 32; i += 8)
            tbuf[ty + i][tx] = I[(long)(c0 + ty + i) * P + p0 + tx];
        __syncthreads();
#pragma unroll
        for (int i = 0; i < 32; i += 8)
            Of[(long)(p0 + ty + i) * AROW + c0 + tx] = __float2half_rn(tbuf[tx][ty + i]);
    } else {
        const int e   = blockIdx.x - 170;   // 0..127
        const int txg = e & 3, tyr = e >> 2;
        const int cg  = blockIdx.y;         // 0..7
        for (int idx = tid; idx < 2304; idx += 256) {
            int cc  = idx / 72;
            int rem = idx - cc * 72;
            int row = rem / 18;
            int col = rem - row * 18;
            int gy = 2 * tyr - 1 + row;
            int gx = txg * 16 - 1 + col;
            float v = 0.f;
            if (gy >= 0 && gy < 64 && gx >= 0 && gx < 64)
                v = q[((long)b * 256 + cg * 32 + cc) * 4096 + gy * 64 + gx];
            s[row][col][cc] = v;
        }
        __syncthreads();
        const int lane = tid & 31, tx = tid >> 5;   // 8 warps = 8 tiles
        float d[4][4];
#pragma unroll
        for (int i = 0; i < 4; i++)
#pragma unroll
            for (int j = 0; j < 4; j++) d[i][j] = s[i][2 * tx + j][lane];
        float t1[4][4];
#pragma unroll
        for (int j = 0; j < 4; j++) {
            t1[0][j] = d[0][j] - d[2][j];
            t1[1][j] = d[1][j] + d[2][j];
            t1[2][j] = d[2][j] - d[1][j];
            t1[3][j] = d[1][j] - d[3][j];
        }
        float V[4][4];
#pragma unroll
        for (int i = 0; i < 4; i++) {
            V[i][0] = t1[i][0] - t1[i][2];
            V[i][1] = t1[i][1] + t1[i][2];
            V[i][2] = t1[i][2] - t1[i][1];
            V[i][3] = t1[i][1] - t1[i][3];
        }
        const int tile = tyr * 32 + txg * 8 + tx;
#pragma unroll
        for (int i = 0; i < 4; i++)
#pragma unroll
            for (int j = 0; j < 4; j++) {
                int t = i * 4 + j;
                long base = ((long)(t * 4 + b) * 1024 + tile) * AROW + cg * 32 + lane;
                g_V[base] = __float2half_rn(V[i][j]);
            }
    }
}

// ---------------------------------------------------------------------------
// Weight prep (one launch): vw, ow, qwT, G-transformed conv weights, bias, bn.
// ---------------------------------------------------------------------------
#define S0 262144
#define S1 (S0 + 65536)
#define S2 (S1 + 65536)
#define S3 (S2 + 1572864)
#define S4 (S3 + 384)
#define S5 (S4 + 256)

__global__ void prep_all(const float* __restrict__ qw, const float* __restrict__ vw,
                         const float* __restrict__ ow,
                         const float* __restrict__ offw, const float* __restrict__ attw,
                         const float* __restrict__ offb, const float* __restrict__ attb,
                         const float* __restrict__ bg, const float* __restrict__ bb,
                         const float* __restrict__ bm, const float* __restrict__ bv)
{
    long i = (long)blockIdx.x * 256 + threadIdx.x;
    if (i < S0) {
        long l = i >> 16, rem = i & 65535;
        long o = rem >> 8, c = rem & 255;
        __half h, lo;
        split_h(vw[i], h, lo);
        long e = l * (256 * WROW) + o * WROW + c;
        g_vw[e] = h; g_vw[e + 256] = lo;
    } else if (i < S1) {
        long j = i - S0;
        long o = j >> 8, c = j & 255;
        __half h, lo;
        split_h(ow[j], h, lo);
        g_ow[o * WROW + c] = h; g_ow[o * WROW + c + 256] = lo;
    } else if (i < S2) {
        long j = i - S1;
        long c = j >> 8, m = j & 255;
        __half h, lo;
        split_h(qw[m * 256 + c], h, lo);
        g_qwT[c * WROW + m] = h; g_qwT[c * WROW + m + 256] = lo;
    } else if (i < S3) {
        long j = i - S2;
        int t = (int)(j / 98304);
        int rem = (int)(j - (long)t * 98304);
        int o = rem >> 8, m = rem & 255;
        int ti = t >> 2, tj = t & 3;
        const float* wsrc = (o < 256) ? offw + ((long)o * 256 + m) * 9
                                      : attw + ((long)(o - 256) * 256 + m) * 9;
        float acc = 0.f;
#pragma unroll
        for (int ki = 0; ki < 3; ki++)
#pragma unroll
            for (int kj = 0; kj < 3; kj++)
                acc += G4[ti][ki] * G4[tj][kj] * wsrc[ki * 3 + kj];
        __half h, lo;
        split_h(acc, h, lo);
        long e = ((long)t * 384 + o) * WROW + m;
        g_W2[e] = h; g_W2[e + 256] = lo;
    } else if (i < S4) {
        long j = i - S3;
        g_cb[j] = (j < 256) ? offb[j] : attb[j - 256];
    } else if (i < S5) {
        long j = i - S4;
        float sc = bg[j] * rsqrtf(bv[j] + BN_EPS);
        g_bns[j] = sc;
        g_bnb[j] = bb[j] - bm[j] * sc;
    }
}

// ---------------------------------------------------------------------------
// Fused winograd output transform + deformable sampling.
// Block = one winograd tile (4 pixels): 384 threads.
//   Phase 1: thread oc computes A^T M A + bias -> smem cv[4][384]
//   Phase 2: 12 warps run 32 (pixel,head) sampler tasks from smem.
// ---------------------------------------------------------------------------
__global__ __launch_bounds__(384)
void wgSample()
{
    __shared__ float scv[4][384];
    const int tile = blockIdx.x;
    const int b    = blockIdx.y;
    const int tid  = threadIdx.x;

    // ---- phase 1: output transform ----
    {
        const int oc = tid;            // 0..383
        const long tstr = (long)4 * 1024 * 384;
        const long base = ((long)b * 1024 + tile) * 384 + oc;
        float m[4][4];
#pragma unroll
        for (int t = 0; t < 16; t++)
            m[t >> 2][t & 3] = g_M[(long)t * tstr + base];
        const float bs = g_cb[oc];
#pragma unroll
        for (int i = 0; i < 2; i++) {
            float t0 = (i == 0) ? (m[0][0] + m[1][0] + m[2][0]) : (m[1][0] - m[2][0] - m[3][0]);
            float t1 = (i == 0) ? (m[0][1] + m[1][1] + m[2][1]) : (m[1][1] - m[2][1] - m[3][1]);
            float t2 = (i == 0) ? (m[0][2] + m[1][2] + m[2][2]) : (m[1][2] - m[2][2] - m[3][2]);
            float t3 = (i == 0) ? (m[0][3] + m[1][3] + m[2][3]) : (m[1][3] - m[2][3] - m[3][3]);
            scv[i * 2 + 0][oc] = t0 + t1 + t2 + bs;
            scv[i * 2 + 1][oc] = t1 - t2 - t3 + bs;
        }
    }
    __syncthreads();

    // ---- phase 2: sampling ----
    const int warp = tid >> 5;
    const int lane = tid & 31;
    const int ty = tile >> 5, tx = tile & 31;

    for (int p = warp; p < 32; p += 12) {
        const int pxl = p >> 3;
        const int h   = p & 7;
        const int py  = 2 * ty + (pxl >> 1);
        const int px  = 2 * tx + (pxl & 1);
        const int pix = py * 64 + px;
        const float refx = -1.f + 2.f * (float)px / 63.f;
        const float refy = -1.f + 2.f * (float)py / 63.f;

        float lg = -INFINITY, ox = 0.f, oy = 0.f;
        if (lane < 16) {
            lg = scv[pxl][256 + h * 16 + lane];
            ox = tanhf(scv[pxl][h * 32 + 2 * lane    ]) * 0.25f;
            oy = tanhf(scv[pxl][h * 32 + 2 * lane + 1]) * 0.25f;
        }
        float mx = lg;
#pragma unroll
        for (int s = 16; s > 0; s >>= 1)
            mx = fmaxf(mx, __shfl_xor_sync(0xFFFFFFFFu, mx, s));
        float e = (lane < 16) ? expf(lg - mx) : 0.f;
        float sum = e;
#pragma unroll
        for (int s = 16; s > 0; s >>= 1)
            sum += __shfl_xor_sync(0xFFFFFFFFu, sum, s);
        float wgt = e / sum;

        const float* vb = g_v + (long)b * VSTRF + h * 32 + lane;
        float acc = 0.f;
#pragma unroll
        for (int i = 0; i < 16; i++) {
            const int lvl = i >> 2;
            const int sz  = 64 >> lvl;
            float aw = __shfl_sync(0xFFFFFFFFu, wgt, i);
            float gx = refx + __shfl_sync(0xFFFFFFFFu, ox, i);
            float gy = refy + __shfl_sync(0xFFFFFFFFu, oy, i);

            float xf = (gx + 1.f) * 0.5f * (float)(sz - 1);
            float yf = (gy + 1.f) * 0.5f * (float)(sz - 1);
            float x0f = floorf(xf), y0f = floorf(yf);
            int x0 = (int)x0f, y0 = (int)y0f;
            int x1 = x0 + 1,  y1 = y0 + 1;
            float wx1 = xf - x0f, wx0 = 1.f - wx1;
            float wy1 = yf - y0f, wy0 = 1.f - wy1;

            const float* vl = vb + c_voff[lvl];
            if (x0 >= 0 && x0 < sz && y0 >= 0 && y0 < sz)
                acc = fmaf(aw * wx0 * wy0, vl[(y0 * sz + x0) * 256], acc);
            if (x1 >= 0 && x1 < sz && y0 >= 0 && y0 < sz)
                acc = fmaf(aw * wx1 * wy0, vl[(y0 * sz + x1) * 256], acc);
            if (x0 >= 0 && x0 < sz && y1 >= 0 && y1 < sz)
                acc = fmaf(aw * wx0 * wy1, vl[(y1 * sz + x0) * 256], acc);
            if (x1 >= 0 && x1 < sz && y1 >= 0 && y1 < sz)
                acc = fmaf(aw * wx1 * wy1, vl[(y1 * sz + x1) * 256], acc);
        }

        g_att[((long)b * HW + pix) * AROW + h * 32 + lane] = __float2half_rn(acc);
    }
}

// ---------------------------------------------------------------------------
// Launch. Main GEMM (winograd + vproj) is the 4th launch (ncu capture slot).
// ---------------------------------------------------------------------------
extern "C" void kernel_launch(void* const* d_in, const int* in_sizes, int n_in,
                              void* d_out, int out_size)
{
    const float* query  = (const float*)d_in[0];
    const float* feat0  = (const float*)d_in[1];
    const float* feat1  = (const float*)d_in[2];
    const float* feat2  = (const float*)d_in[3];
    const float* feat3  = (const float*)d_in[4];
    const float* q_w    = (const float*)d_in[5];
    const float* v_w    = (const float*)d_in[6];
    const float* out_w  = (const float*)d_in[7];
    const float* off_w  = (const float*)d_in[8];
    const float* off_b  = (const float*)d_in[9];
    const float* attn_w = (const float*)d_in[10];
    const float* attn_b = (const float*)d_in[11];
    const float* bn_g   = (const float*)d_in[12];
    const float* bn_b   = (const float*)d_in[13];
    const float* bn_m   = (const float*)d_in[14];
    const float* bn_v   = (const float*)d_in[15];
    float* out = (float*)d_out;

    cudaFuncSetAttribute(mm_all<0>, cudaFuncAttributeMaxDynamicSharedMemorySize, DSMEM_SZ);
    cudaFuncSetAttribute(mm_all<1>, cudaFuncAttributeMaxDynamicSharedMemorySize, DSMEM_SZ);
    cudaFuncSetAttribute(mm_all<3>, cudaFuncAttributeMaxDynamicSharedMemorySize, DSMEM_SZ);

    // 1. weight prep
    prep_all<<<(S5 + 255) / 256, 256>>>(q_w, v_w, out_w, off_w, attn_w,
                                        off_b, attn_b, bn_g, bn_b, bn_m, bn_v);
    // 2. feat transposes + winograd input transform of query
    prepActs<<<dim3(298, 8, BATCH), 256>>>(query, feat0, feat1, feat2, feat3);

    // 3. compose winograd weights (3-term, split A)
    mm_all<0><<<dim3(48, 2, 1), 256, DSMEM_SZ>>>(nullptr, nullptr);

    // 4. merged winograd-M + vproj GEMM (2-term)  <-- ncu capture slot
    mm_all<1><<<dim3(470, 1, BATCH), 256, DSMEM_SZ>>>(nullptr, nullptr);

    // 5. fused winograd output transform + sampling
    wgSample<<<dim3(1024, BATCH), 384>>>();

    // 6. output projection + residual + BN + SiLU (2-term)
    mm_all<3><<<dim3(32, 2, BATCH), 256, DSMEM_SZ>>>(query, out);
}